// round 6
// baseline (speedup 1.0000x reference)
#include <cuda_runtime.h>

#define NN 512          // T = U = 512
#define NT 256          // 256 threads, 2 interleaved columns each, 8 warps
#define C_CONST 1.0f
#define GEPS 1e-9f
#define MAXB 64

__device__ float g_costs[MAXB];
__device__ int g_ctr = 0;

__device__ __forceinline__ void st_release64(unsigned long long* p, unsigned long long v) {
    unsigned a = (unsigned)__cvta_generic_to_shared(p);
    asm volatile("st.release.cta.shared.b64 [%0], %1;" :: "r"(a), "l"(v) : "memory");
}
__device__ __forceinline__ unsigned long long ld_acquire64(unsigned long long* p) {
    unsigned a = (unsigned)__cvta_generic_to_shared(p);
    unsigned long long v;
    asm volatile("ld.acquire.cta.shared.b64 %0, [%1];" : "=l"(v) : "r"(a) : "memory");
    return v;
}

// trans with a, b given plus precomputed A=a^2, B=b^2 (B shared with match)
__device__ __forceinline__ float transf(float a, float b, float A, float B) {
    float u = a * b;
    float w = 0.5f * (1.0f + u * rsqrtf(fmaf(u, u, GEPS)));   // 1 - gate
    float mn = fminf(A, B);
    float mx = fmaxf(A, B);
    float sm = mn - __logf(1.0f + __expf(mn - mx));           // softmin2
    return fmaf(w, sm, C_CONST);
}

// softmin3 with the min-arm's exp folded to 1 (exact), INF-safe for boundary arms
__device__ __forceinline__ float softmin3f(float a, float b, float c) {
    float mn    = fminf(a, fminf(b, c));
    float mx    = fmaxf(a, fmaxf(b, c));
    float ab_mn = fminf(a, b);
    float ab_mx = fmaxf(a, b);
    float md    = fmaxf(ab_mn, fminf(ab_mx, c));              // median
    float s = 1.0f + __expf(mn - md) + __expf(mn - mx);       // exp(mn-mn)==1
    return mn - __logf(s);
}

__global__ __launch_bounds__(NT, 1)
void soft_msm_kernel(const float* __restrict__ x, const float* __restrict__ y,
                     float* __restrict__ out, int B) {
    __shared__ float sxe[NT], sxo[NT];            // x even / odd indices
    __shared__ float saue[NT], sauo[NT];          // x[i]-x[i-1], split by parity of i
    __shared__ unsigned long long bnd[7][512];    // (tag<<32 | valbits) boundary handoff rings

    const int b    = blockIdx.x;
    const int t    = threadIdx.x;
    const int w    = t >> 5;
    const int lane = t & 31;
    const float* xb = x + b * NN;
    const float* yb = y + b * NN;

    // column constants: jE = 2t, jO = 2t+1
    const float yE   = yb[2 * t];
    const float yO   = yb[2 * t + 1];
    const float yEm1 = (t > 0) ? yb[2 * t - 1] : 0.0f;
    const float alE  = yE - yEm1;
    const float alO  = yO - yE;
    const float alE2 = alE * alE;
    const float alO2 = alO * alO;

    const float xe = xb[2 * t];
    const float xo = xb[2 * t + 1];
    sxe[t] = xe; sxo[t] = xo;

    // init boundary ring tags to -1
    for (int i = t; i < 7 * 512; i += NT)
        ((unsigned long long*)bnd)[i] = 0xFFFFFFFF00000000ull;
    __syncthreads();
    saue[t] = (t > 0) ? (xe - sxo[t - 1]) : 0.0f;   // sau[2t]
    sauo[t] = xo - xe;                               // sau[2t+1]
    const float x0 = sxe[0];
    __syncthreads();

    // carried DP state
    float prevE  = 0.0f;   // C[.., jE] @ d-1
    float prevO  = 0.0f;   // C[.., jO] @ d-1
    float prev2E = 0.0f;   // C[.., jE] @ d-2  (diag for odd cell)
    float pdiagE = 0.0f;   // C[.., jE-1] @ d-2 (diag for even cell)
    if (t == 0) { float d0 = x0 - yE; prevE = d0 * d0; }     // C[0,0], diagonal 0

    const int jE = 2 * t;
    const float INF = __int_as_float(0x7f800000);

    const int D0     = 64 * w;
    const int dStart = (w == 0) ? 1 : D0;
    const int dEnd   = D0 + 574;          // warp 7 ends at 1022

    for (int d = dStart; d <= dEnd; ++d) {
        // left neighbor of even col on diagonal d-1 = prev thread's odd col
        float fromLeft = __shfl_up_sync(0xffffffffu, prevO, 1);
        if (lane == 0 && w > 0 && d <= D0 + 511) {
            // producer (warp w-1) writes diag d-1 into slot (d-1)&511, tag = d-1
            unsigned long long pk = ld_acquire64(&bnd[w - 1][(d - 1) & 511]);
            while ((int)(pk >> 32) != d - 1) {
                __nanosleep(20);
                pk = ld_acquire64(&bnd[w - 1][(d - 1) & 511]);
            }
            fromLeft = __uint_as_float((unsigned)pk);
        }

        // parity-split x arrays: parity(iE) == parity(d)
        const float* xEa = (d & 1) ? sxo  : sxe;
        const float* xOa = (d & 1) ? sxe  : sxo;
        const float* sEa = (d & 1) ? sauo : saue;
        const float* sOa = (d & 1) ? saue : sauo;

        const int iE = d - jE;
        const int iO = iE - 1;
        const bool vE = (iE >= 0) && (iE < NN);
        const bool vO = (iO >= 0) && (iO < NN);
        const int iEc = min(max(iE, 0), NN - 1);
        const int iOc = min(max(iO, 0), NN - 1);
        const float xiE = xEa[iEc >> 1];
        const float xiO = xOa[iOc >> 1];
        const float saE = sEa[iEc >> 1];
        const float saO = sOa[iOc >> 1];

        // ---- even cell (iE, jE) ----
        float bxE = xiE - yE;
        float mE  = bxE * bxE;
        float utE = transf(saE,  bxE, saE * saE, mE);   // trans(x_i, x_{i-1}, y_j)
        float ltE = transf(alE, -bxE, alE2,      mE);   // trans(y_j, y_{j-1}, x_i)
        float dd = pdiagE   + mE;
        float du = prevE    + utE;
        float cl = fromLeft + ltE;
        if (jE == 0) { dd = INF; cl = INF; }            // col-0 boundary
        if (iE == 0) { dd = INF; du = INF; }            // row-0 boundary
        float cE = softmin3f(dd, du, cl);

        // ---- odd cell (iO, jO): neighbors are own registers ----
        float bxO = xiO - yO;
        float mO  = bxO * bxO;
        float utO = transf(saO,  bxO, saO * saO, mO);
        float ltO = transf(alO, -bxO, alO2,      mO);
        float ddo = prev2E + mO;
        float duo = prevO  + utO;
        float clo = prevE  + ltO;                       // left = even col @ d-1
        if (iO == 0) { ddo = INF; duo = INF; }
        float cO = softmin3f(ddo, duo, clo);

        // state rotation (compute-then-update; predicated on validity)
        if (vE) { pdiagE = fromLeft; prev2E = prevE; prevE = cE; }
        if (vO) {
            prevO = cO;
            if (lane == 31 && w < 7)
                st_release64(&bnd[w][d & 511],
                             ((unsigned long long)(unsigned)d << 32) |
                             (unsigned long long)__float_as_uint(cO));
        }
    }

    // fused mean-reduction: last CTA to arrive sums and writes out
    if (t == NT - 1) {
        g_costs[b] = prevO;                 // C[511,511]
        __threadfence();
        int old = atomicAdd(&g_ctr, 1);
        if (old == B - 1) {
            __threadfence();
            float s = 0.0f;
            for (int i = 0; i < B; ++i)
                s += *((volatile float*)&g_costs[i]);
            out[0] = s * (1.0f / (float)B);
            atomicExch(&g_ctr, 0);          // reset for next graph replay
        }
    }
}

extern "C" void kernel_launch(void* const* d_in, const int* in_sizes, int n_in,
                              void* d_out, int out_size) {
    const float* x = (const float*)d_in[0];
    const float* y = (const float*)d_in[1];
    int B = in_sizes[0] / NN;   // 64
    if (B > MAXB) B = MAXB;
    soft_msm_kernel<<<B, NT>>>(x, y, (float*)d_out, B);
}